// round 15
// baseline (speedup 1.0000x reference)
#include <cuda_runtime.h>
#include <cuda_bf16.h>
#include <cstdint>

#define T_STEPS 500
#define BATCH   512
#define CIN     128
#define NHID    512
#define NBLK    512          // independent blocks; 1 batch row each (4 blocks/SM)
#define NT      128          // warps 0-1: layer1 (8 neurons/thr), warps 2-3: layer2
#define ZROW    512          // sentinel row index (all zeros) for list padding

// ---------------- static device scratch (no allocations allowed) ----------------
__device__ float g_xtr[(size_t)T_STEPS * BATCH * CIN];    // [(t*B+b)][c]
__device__ float g_in1[(size_t)T_STEPS * BATCH * NHID];   // x@W1^T + b1 + br2
__device__ float g_W1T[CIN * NHID];                       // [c][n]
// combined gather table, lo/hi-split layout. Row j (1024 floats):
//   [gt*4 .. gt*4+3]        = Wr2[gt*8   .. gt*8+3][j]   (lo,  gt = 0..63)
//   [256 + gt*4 .. +3]      = Wr2[gt*8+4 .. gt*8+7][j]   (hi)
//   [512 + gt*4 .. +3]      = W2 [gt*8   .. gt*8+3][j]
//   [768 + gt*4 .. +3]      = W2 [gt*8+4 .. gt*8+7][j]
// rows j = 512..515 stay zero (sentinel padding rows; .bss zero-init, never written)
__device__ float g_Wab[(size_t)(ZROW + 4) * 1024];

// packed-f32x2 helpers: two independent IEEE fma.rn.f32 per instruction -> bit-exact
#define FMA2(d, a, b) asm("fma.rn.f32x2 %0, %1, %2, %0;" : "+l"(d) : "l"(a), "l"(b))
#define PACK2(d, s)   asm("mov.b64 %0, {%1, %1};" : "=l"(d) : "r"(s))

// ---------------- x[b][c][t] -> g_xtr[(t*B+b)][c] -------------------------------
__global__ void k_transpose_x(const float* __restrict__ x) {
    __shared__ float tile[32][33];
    int b = blockIdx.z;
    int t0 = blockIdx.x * 32, c0 = blockIdx.y * 32;
    int tx = threadIdx.x, ty = threadIdx.y;
#pragma unroll
    for (int i = 0; i < 32; i += 8) {
        int c = c0 + ty + i, t = t0 + tx;
        if (t < T_STEPS && c < CIN)
            tile[ty + i][tx] = x[((size_t)b * CIN + c) * T_STEPS + t];
    }
    __syncthreads();
#pragma unroll
    for (int i = 0; i < 32; i += 8) {
        int t = t0 + ty + i, c = c0 + tx;
        if (t < T_STEPS && c < CIN)
            g_xtr[((size_t)t * BATCH + b) * CIN + c] = tile[tx][ty + i];
    }
}

// ---------------- merged prep: W1 transpose + Wab pack (lo/hi split) --------------
__global__ void k_prep(const float* __restrict__ W1,
                       const float* __restrict__ Wr2, const float* __restrict__ W2) {
    int blk = blockIdx.x;
    if (blk < 256) {
        int i = blk * 256 + threadIdx.x;       // 0 .. 512*128-1
        int j = i >> 7, q = i & 127, n0 = q * 4;
        float4 a, b;
        a.x = Wr2[(size_t)(n0 + 0) * NHID + j];
        a.y = Wr2[(size_t)(n0 + 1) * NHID + j];
        a.z = Wr2[(size_t)(n0 + 2) * NHID + j];
        a.w = Wr2[(size_t)(n0 + 3) * NHID + j];
        b.x = W2[(size_t)(n0 + 0) * NHID + j];
        b.y = W2[(size_t)(n0 + 1) * NHID + j];
        b.z = W2[(size_t)(n0 + 2) * NHID + j];
        b.w = W2[(size_t)(n0 + 3) * NHID + j];
        int gt = q >> 1;
        int half = q & 1;                      // 0 = lo, 1 = hi
        size_t base = (size_t)j * 1024 + half * 256 + gt * 4;
        *(float4*)(g_Wab + base) = a;          // Wr2 section
        *(float4*)(g_Wab + base + 512) = b;    // W2 section
    } else {
        int i = (blk - 256) * 256 + threadIdx.x;   // 0 .. CIN*NHID-1
        int c = i >> 9, n = i & 511;
        g_W1T[(size_t)c * NHID + n] = W1[(size_t)n * CIN + c];
    }
}

// ---------------- in1 = xtr @ W1T + (b1 + br2); 128x128 tile, 8x8/thread ---------
// Inner product via fma.rn.f32x2 (FFMA2): two independent fma.rn.f32 per
// instruction, identical per-element k-order -> bit-exact vs scalar FFMA.
// Grid mapping keeps N-tiles fastest so consecutive blocks share the A tile in L2.
__global__ __launch_bounds__(256)
void k_gemm_in1(const float* __restrict__ b1, const float* __restrict__ br2) {
    __shared__ float As[16][132];   // [k][m]
    __shared__ float Bs[16][132];   // [k][n]
    const float* A = g_xtr;
    const float* B = g_W1T;
    int bm = blockIdx.y * 128, bn = blockIdx.x * 128;
    int tid = threadIdx.x;
    int tx = tid & 15, ty = tid >> 4;
    int arow = tid >> 1, acol = (tid & 1) * 8;
    int brow = tid >> 4, bcol = (tid & 15) * 8;

    // packed accumulators: acc2[i][j] = (acc[i][2j], acc[i][2j+1])
    unsigned long long acc2[8][4];
#pragma unroll
    for (int i = 0; i < 8; i++)
#pragma unroll
        for (int j = 0; j < 4; j++) acc2[i][j] = 0ull;

    for (int k0 = 0; k0 < CIN; k0 += 16) {
        float4 v0 = *(const float4*)(A + (size_t)(bm + arow) * CIN + k0 + acol);
        float4 v1 = *(const float4*)(A + (size_t)(bm + arow) * CIN + k0 + acol + 4);
        As[acol + 0][arow] = v0.x;
        As[acol + 1][arow] = v0.y;
        As[acol + 2][arow] = v0.z;
        As[acol + 3][arow] = v0.w;
        As[acol + 4][arow] = v1.x;
        As[acol + 5][arow] = v1.y;
        As[acol + 6][arow] = v1.z;
        As[acol + 7][arow] = v1.w;
        *(float4*)&Bs[brow][bcol] =
            *(const float4*)(B + (size_t)(k0 + brow) * NHID + bn + bcol);
        *(float4*)&Bs[brow][bcol + 4] =
            *(const float4*)(B + (size_t)(k0 + brow) * NHID + bn + bcol + 4);
        __syncthreads();
#pragma unroll
        for (int k = 0; k < 16; k++) {
            float4 av0 = *(const float4*)&As[k][ty * 8];
            float4 av1 = *(const float4*)&As[k][ty * 8 + 4];
            // B fragment as packed pairs (16B-aligned SMEM)
            unsigned long long b01 = *(const unsigned long long*)&Bs[k][tx * 4];
            unsigned long long b23 = *(const unsigned long long*)&Bs[k][tx * 4 + 2];
            unsigned long long b45 = *(const unsigned long long*)&Bs[k][64 + tx * 4];
            unsigned long long b67 = *(const unsigned long long*)&Bs[k][64 + tx * 4 + 2];
            float a[8] = {av0.x, av0.y, av0.z, av0.w, av1.x, av1.y, av1.z, av1.w};
#pragma unroll
            for (int i = 0; i < 8; i++) {
                unsigned long long aa;
                PACK2(aa, __float_as_uint(a[i]));
                FMA2(acc2[i][0], aa, b01);
                FMA2(acc2[i][1], aa, b23);
                FMA2(acc2[i][2], aa, b45);
                FMA2(acc2[i][3], aa, b67);
            }
        }
        __syncthreads();
    }
    int col0 = bn + tx * 4;
    int col1 = bn + 64 + tx * 4;
    float bb[8];
#pragma unroll
    for (int j = 0; j < 4; j++) {
        bb[j] = b1[col0 + j] + br2[col0 + j];
        bb[4 + j] = b1[col1 + j] + br2[col1 + j];
    }
#pragma unroll
    for (int i = 0; i < 8; i++) {
        size_t row = (size_t)(bm + ty * 8 + i);
        float2 p0 = *(float2*)&acc2[i][0];
        float2 p1 = *(float2*)&acc2[i][1];
        float2 p2 = *(float2*)&acc2[i][2];
        float2 p3 = *(float2*)&acc2[i][3];
        float4 o0, o1;
        o0.x = p0.x + bb[0];
        o0.y = p0.y + bb[1];
        o0.z = p1.x + bb[2];
        o0.w = p1.y + bb[3];
        o1.x = p2.x + bb[4];
        o1.y = p2.y + bb[5];
        o1.z = p3.x + bb[6];
        o1.w = p3.y + bb[7];
        *(float4*)(g_in1 + row * NHID + col0) = o0;
        *(float4*)(g_in1 + row * NHID + col1) = o1;
    }
}

// ---------------- helpers ----------------------------------------------------------
__device__ __forceinline__ void acc_add(float4& a, const float4& v) {
    a.x += v.x; a.y += v.y; a.z += v.z; a.w += v.w;
}

// 8-neuron-wide walk over a padded list (round-11 form: no manual pipelining —
// the 128-reg budget has no headroom; spills cost more than the overlap gains).
// W points at (g_Wab + tableOff + gt*4); lo at +0, hi at +256 floats (coalesced).
// Accumulation: ascending j, per-neuron order identical to a simple loop -> bit-exact.
__device__ __forceinline__ void walk8(const unsigned short* __restrict__ L, int c,
                                      const float* __restrict__ W,
                                      float4& lo, float4& hi) {
    for (int k = 0; k < c; k += 4) {
        ushort4 jj = *(const ushort4*)(L + k);
        const float* p0 = W + ((int)jj.x << 10);
        const float* p1 = W + ((int)jj.y << 10);
        const float* p2 = W + ((int)jj.z << 10);
        const float* p3 = W + ((int)jj.w << 10);
        float4 l0 = __ldg((const float4*)p0), h0 = __ldg((const float4*)(p0 + 256));
        float4 l1 = __ldg((const float4*)p1), h1 = __ldg((const float4*)(p1 + 256));
        float4 l2 = __ldg((const float4*)p2), h2 = __ldg((const float4*)(p2 + 256));
        float4 l3 = __ldg((const float4*)p3), h3 = __ldg((const float4*)(p3 + 256));
        acc_add(lo, l0); acc_add(hi, h0);
        acc_add(lo, l1); acc_add(hi, h1);
        acc_add(lo, l2); acc_add(hi, h2);
        acc_add(lo, l3); acc_add(hi, h3);
    }
}

// ballot-based ordered compaction of an 8-bit spike byte (lane-major, bit-minor
// = ascending j within the warp's 256-neuron segment). Returns padded count.
__device__ __forceinline__ int compact8(unsigned nib, int lane, int n0,
                                        unsigned short* __restrict__ Lw) {
    unsigned lt = (1u << lane) - 1u;
    int base = 0, ctot = 0;
#pragma unroll
    for (int b = 0; b < 8; b++) {
        unsigned B = __ballot_sync(0xffffffffu, (nib >> b) & 1u);
        base += __popc(B & lt);
        ctot += __popc(B);
    }
    unsigned m = nib;
    while (m) {
        int b = __ffs(m) - 1;
        m &= m - 1u;
        Lw[base++] = (unsigned short)(n0 + b);
    }
    int cpad = (ctot + 3) & ~3;
    if (lane < cpad - ctot) Lw[ctot + lane] = (unsigned short)ZROW;
    return cpad;
}

// LIF update for 4 neurons; expressions textually identical to prior rounds.
__device__ __forceinline__ unsigned lif4(float4& mem, float4& sp, float4& cnt,
                                         const float4 tau, const float4 vth,
                                         const float4 inp) {
    mem.x = tau.x * mem.x * (1.f - sp.x) + inp.x;
    mem.y = tau.y * mem.y * (1.f - sp.y) + inp.y;
    mem.z = tau.z * mem.z * (1.f - sp.z) + inp.z;
    mem.w = tau.w * mem.w * (1.f - sp.w) + inp.w;
    float sx = (mem.x > vth.x) ? 1.f : 0.f;
    float sy = (mem.y > vth.y) ? 1.f : 0.f;
    float sz = (mem.z > vth.z) ? 1.f : 0.f;
    float sw = (mem.w > vth.w) ? 1.f : 0.f;
    sp = make_float4(sx, sy, sz, sw);
    cnt.x += sx; cnt.y += sy; cnt.z += sz; cnt.w += sw;
    return (sx > 0.f ? 1u : 0u) | (sy > 0.f ? 2u : 0u) |
           (sz > 0.f ? 4u : 0u) | (sw > 0.f ? 8u : 0u);
}

// ---------------- persistent per-block recurrent kernel (no grid sync) -----------
// Warps 0-1: layer 1.  Warps 2-3: layer 2 + readout.  They run CONCURRENTLY:
// both layers' inputs (s1[p-1], s2[p-2], in1[p]) are available at phase start.
__global__ __launch_bounds__(NT, 4)
void k_rsnn(const float* __restrict__ W4,
            const float* __restrict__ b2, const float* __restrict__ br2,
            const float* __restrict__ b4,
            const float* __restrict__ Vth1, const float* __restrict__ tau1,
            const float* __restrict__ Vth2, const float* __restrict__ tau2,
            const float* __restrict__ tau_out,
            float* __restrict__ out) {
    __shared__ float2 W4sh[NHID];
    __shared__ __align__(16) unsigned short slist1[2][2][256];  // [buf][warpseg]
    __shared__ __align__(16) unsigned short slist2[2][2][256];
    __shared__ int scnt1[2][2];
    __shared__ int scnt2[2][2];
    __shared__ float redx[2][2];
    __shared__ float redy[2][2];

    const int tid = threadIdx.x;
    const int grp = tid >> 6;                // 0 = layer1, 1 = layer2
    const int gt = tid & 63;                 // thread in group
    const int n0 = gt * 8;                   // neurons n0..n0+7 (of its layer)
    const int lane = tid & 31;
    const int gw = (tid >> 5) & 1;           // warp within group (segment id)
    const int rowg = blockIdx.x;             // global batch row

    for (int i = tid; i < NHID; i += NT)
        W4sh[i] = make_float2(W4[i], W4[NHID + i]);
    if (tid < 4) {
        ((int*)scnt1)[tid] = 0;
        ((int*)scnt2)[tid] = 0;
    }
    __syncthreads();

    const float4 z4 = make_float4(0.f, 0.f, 0.f, 0.f);
    // per-group parameters for this thread's 8 neurons
    float4 tau_lo, tau_hi, vth_lo, vth_hi, bias_lo = z4, bias_hi = z4;
    if (grp == 0) {
        tau_lo = *(const float4*)(tau1 + n0);
        tau_hi = *(const float4*)(tau1 + n0 + 4);
        vth_lo = *(const float4*)(Vth1 + n0);
        vth_hi = *(const float4*)(Vth1 + n0 + 4);
    } else {
        tau_lo = *(const float4*)(tau2 + n0);
        tau_hi = *(const float4*)(tau2 + n0 + 4);
        vth_lo = *(const float4*)(Vth2 + n0);
        vth_hi = *(const float4*)(Vth2 + n0 + 4);
        bias_lo.x = b2[n0 + 0] + br2[n0 + 0];
        bias_lo.y = b2[n0 + 1] + br2[n0 + 1];
        bias_lo.z = b2[n0 + 2] + br2[n0 + 2];
        bias_lo.w = b2[n0 + 3] + br2[n0 + 3];
        bias_hi.x = b2[n0 + 4] + br2[n0 + 4];
        bias_hi.y = b2[n0 + 5] + br2[n0 + 5];
        bias_hi.z = b2[n0 + 6] + br2[n0 + 6];
        bias_hi.w = b2[n0 + 7] + br2[n0 + 7];
    }

    float4 mem_lo = z4, mem_hi = z4, sp_lo = z4, sp_hi = z4, cnt_lo = z4, cnt_hi = z4;
    unsigned nib2_prev = 0u;                 // layer-2 group: s2[t] byte from prev phase
    float memo_x = 0.f, memo_y = 0.f;        // thread 64 only
    const float to0 = tau_out[0], to1 = tau_out[1];
    const float b40 = b4[0], b41 = b4[1];

    const float* __restrict__ WAB = g_Wab;
    const float* Wrec = WAB + gt * 4;        // Wr2 slice (lo at +0, hi at +256)
    const float* Wff  = WAB + 512 + gt * 4;  // W2 slice

    for (int p = 0; p <= T_STEPS + 1; p++) {
        const int rb1 = (p + 1) & 1;          // buf holding s1[p-1]
        const int rb2 = p & 1;                // buf holding s2[p-2]

        if (grp == 0) {
            // ================= LAYER 1, t = p =================
            if (p < T_STEPS) {
                float4 i1_lo = __ldcg((const float4*)(g_in1 + ((size_t)p * BATCH + rowg) * NHID + n0));
                float4 i1_hi = __ldcg((const float4*)(g_in1 + ((size_t)p * BATCH + rowg) * NHID + n0 + 4));
                float4 a_lo = z4, a_hi = z4;
#pragma unroll
                for (int w = 0; w < 2; w++)
                    walk8(slist1[rb1][w], scnt1[rb1][w], Wrec, a_lo, a_hi);
                i1_lo.x += a_lo.x; i1_lo.y += a_lo.y; i1_lo.z += a_lo.z; i1_lo.w += a_lo.w;
                i1_hi.x += a_hi.x; i1_hi.y += a_hi.y; i1_hi.z += a_hi.z; i1_hi.w += a_hi.w;
                unsigned nib = lif4(mem_lo, sp_lo, cnt_lo, tau_lo, vth_lo, i1_lo);
                nib |= lif4(mem_hi, sp_hi, cnt_hi, tau_hi, vth_hi, i1_hi) << 4;
                int cpad = compact8(nib, lane, n0, slist1[p & 1][gw]);
                if (lane == 0) scnt1[p & 1][gw] = cpad;
            }
        } else {
            // ================= LAYER 2, t = p-1, + readout t = p-2 =================
            unsigned nib2_new = 0u;
            if (p >= 1 && p <= T_STEPS) {
                float4 r_lo = z4, r_hi = z4;     // Wr2 @ s2[p-2]
                float4 f_lo = z4, f_hi = z4;     // W2  @ s1[p-1]
#pragma unroll
                for (int w = 0; w < 2; w++)
                    walk8(slist2[rb2][w], scnt2[rb2][w], Wrec, r_lo, r_hi);
#pragma unroll
                for (int w = 0; w < 2; w++)
                    walk8(slist1[rb1][w], scnt1[rb1][w], Wff, f_lo, f_hi);
                float4 i2_lo, i2_hi;
                i2_lo.x = f_lo.x + r_lo.x + bias_lo.x;
                i2_lo.y = f_lo.y + r_lo.y + bias_lo.y;
                i2_lo.z = f_lo.z + r_lo.z + bias_lo.z;
                i2_lo.w = f_lo.w + r_lo.w + bias_lo.w;
                i2_hi.x = f_hi.x + r_hi.x + bias_hi.x;
                i2_hi.y = f_hi.y + r_hi.y + bias_hi.y;
                i2_hi.z = f_hi.z + r_hi.z + bias_hi.z;
                i2_hi.w = f_hi.w + r_hi.w + bias_hi.w;
                nib2_new = lif4(mem_lo, sp_lo, cnt_lo, tau_lo, vth_lo, i2_lo);
                nib2_new |= lif4(mem_hi, sp_hi, cnt_hi, tau_hi, vth_hi, i2_hi) << 4;
                int cpad = compact8(nib2_new, lane, n0, slist2[(p + 1) & 1][gw]);
                if (lane == 0) scnt2[(p + 1) & 1][gw] = cpad;
            }

            // readout partials for t = p-2 (uses nib2_prev = s2[p-2])
            {
                float ax = 0.f, ay = 0.f;
                unsigned nb = nib2_prev;
#pragma unroll
                for (int b = 0; b < 8; b++) {
                    if (nb & (1u << b)) {
                        float2 t = W4sh[n0 + b];
                        ax += t.x;
                        ay += t.y;
                    }
                }
#pragma unroll
                for (int off = 16; off > 0; off >>= 1) {
                    ax += __shfl_down_sync(0xffffffffu, ax, off);
                    ay += __shfl_down_sync(0xffffffffu, ay, off);
                }
                if (lane == 0) {
                    redx[p & 1][gw] = ax;
                    redy[p & 1][gw] = ay;
                }
            }
            nib2_prev = nib2_new;
        }

        __syncthreads();   // the ONLY sync per phase (4 warps)

        // ---- finalize readout t = p-2 (one thread of layer-2 group) ----
        if (p >= 2 && tid == 64) {
            int par = p & 1;
            float ax = redx[par][0] + redx[par][1];
            float ay = redy[par][0] + redy[par][1];
            memo_x = to0 * memo_x + ax + b40;
            memo_y = to1 * memo_y + ay + b41;
            int t = p - 2;
            out[(size_t)rowg * (2 * T_STEPS) + t] = memo_x;
            out[(size_t)rowg * (2 * T_STEPS) + T_STEPS + t] = memo_y;
        }
    }

    // ---- spike-count outputs ----
    const float inv = 1.f / (float)T_STEPS;
    float* sc1 = out + (size_t)BATCH * 2 * T_STEPS;
    float* sc2 = sc1 + (size_t)BATCH * NHID;
    float* dst = (grp == 0) ? sc1 : sc2;
    *(float4*)(dst + (size_t)rowg * NHID + n0) =
        make_float4(cnt_lo.x * inv, cnt_lo.y * inv, cnt_lo.z * inv, cnt_lo.w * inv);
    *(float4*)(dst + (size_t)rowg * NHID + n0 + 4) =
        make_float4(cnt_hi.x * inv, cnt_hi.y * inv, cnt_hi.z * inv, cnt_hi.w * inv);
}

// ---------------- launch ----------------------------------------------------------
extern "C" void kernel_launch(void* const* d_in, const int* in_sizes, int n_in,
                              void* d_out, int out_size) {
    (void)in_sizes; (void)n_in; (void)out_size;
    const float* x    = (const float*)d_in[0];
    const float* W1   = (const float*)d_in[1];
    const float* b1   = (const float*)d_in[2];
    const float* W2   = (const float*)d_in[3];
    const float* b2   = (const float*)d_in[4];
    const float* Wr2  = (const float*)d_in[5];
    const float* br2  = (const float*)d_in[6];
    // d_in[7..10]: W3, b3, Wr3, br3 — dead (layer 3 never reaches outputs)
    const float* W4   = (const float*)d_in[11];
    const float* b4   = (const float*)d_in[12];
    const float* Vth1 = (const float*)d_in[13];
    const float* tau1 = (const float*)d_in[14];
    const float* Vth2 = (const float*)d_in[15];
    const float* tau2 = (const float*)d_in[16];
    // d_in[17..18]: Vth3, tau3 — dead
    const float* tau_out = (const float*)d_in[19];
    float* out = (float*)d_out;

    k_transpose_x<<<dim3((T_STEPS + 31) / 32, CIN / 32, BATCH), dim3(32, 8)>>>(x);
    k_prep<<<512, 256>>>(W1, Wr2, W2);
    // N-tiles fastest -> consecutive blocks reuse the same A tile via L2
    k_gemm_in1<<<dim3(NHID / 128, (T_STEPS * BATCH) / 128), 256>>>(b1, br2);
    k_rsnn<<<NBLK, NT>>>(W4, b2, br2, b4, Vth1, tau1, Vth2, tau2, tau_out, out);
}

// round 16
// speedup vs baseline: 1.5199x; 1.5199x over previous
#include <cuda_runtime.h>
#include <cuda_bf16.h>
#include <cstdint>

#define T_STEPS 500
#define BATCH   512
#define CIN     128
#define NHID    512
#define NBLK    512          // independent blocks; 1 batch row each (4 blocks/SM)
#define NT      128          // warps 0-1: layer1 (8 neurons/thr), warps 2-3: layer2
#define ZROW    512          // sentinel row index (all zeros) for list padding

// ---------------- static device scratch (no allocations allowed) ----------------
__device__ float g_xtr[(size_t)T_STEPS * BATCH * CIN];    // [(t*B+b)][c]
__device__ float g_in1[(size_t)T_STEPS * BATCH * NHID];   // x@W1^T + b1 + br2
__device__ float g_W1T[CIN * NHID];                       // [c][n]
// combined gather table, lo/hi-split layout. Row j (1024 floats):
//   [gt*4 .. gt*4+3]        = Wr2[gt*8   .. gt*8+3][j]   (lo,  gt = 0..63)
//   [256 + gt*4 .. +3]      = Wr2[gt*8+4 .. gt*8+7][j]   (hi)
//   [512 + gt*4 .. +3]      = W2 [gt*8   .. gt*8+3][j]
//   [768 + gt*4 .. +3]      = W2 [gt*8+4 .. gt*8+7][j]
// rows j = 512..515 stay zero (sentinel padding rows; .bss zero-init, never written)
__device__ float g_Wab[(size_t)(ZROW + 4) * 1024];

// ---------------- x[b][c][t] -> g_xtr[(t*B+b)][c] -------------------------------
__global__ void k_transpose_x(const float* __restrict__ x) {
    __shared__ float tile[32][33];
    int b = blockIdx.z;
    int t0 = blockIdx.x * 32, c0 = blockIdx.y * 32;
    int tx = threadIdx.x, ty = threadIdx.y;
#pragma unroll
    for (int i = 0; i < 32; i += 8) {
        int c = c0 + ty + i, t = t0 + tx;
        if (t < T_STEPS && c < CIN)
            tile[ty + i][tx] = x[((size_t)b * CIN + c) * T_STEPS + t];
    }
    __syncthreads();
#pragma unroll
    for (int i = 0; i < 32; i += 8) {
        int t = t0 + ty + i, c = c0 + tx;
        if (t < T_STEPS && c < CIN)
            g_xtr[((size_t)t * BATCH + b) * CIN + c] = tile[tx][ty + i];
    }
}

// ---------------- merged prep: W1 transpose + Wab pack (lo/hi split) --------------
__global__ void k_prep(const float* __restrict__ W1,
                       const float* __restrict__ Wr2, const float* __restrict__ W2) {
    int blk = blockIdx.x;
    if (blk < 256) {
        int i = blk * 256 + threadIdx.x;       // 0 .. 512*128-1
        int j = i >> 7, q = i & 127, n0 = q * 4;
        float4 a, b;
        a.x = Wr2[(size_t)(n0 + 0) * NHID + j];
        a.y = Wr2[(size_t)(n0 + 1) * NHID + j];
        a.z = Wr2[(size_t)(n0 + 2) * NHID + j];
        a.w = Wr2[(size_t)(n0 + 3) * NHID + j];
        b.x = W2[(size_t)(n0 + 0) * NHID + j];
        b.y = W2[(size_t)(n0 + 1) * NHID + j];
        b.z = W2[(size_t)(n0 + 2) * NHID + j];
        b.w = W2[(size_t)(n0 + 3) * NHID + j];
        int gt = q >> 1;
        int half = q & 1;                      // 0 = lo, 1 = hi
        size_t base = (size_t)j * 1024 + half * 256 + gt * 4;
        *(float4*)(g_Wab + base) = a;          // Wr2 section
        *(float4*)(g_Wab + base + 512) = b;    // W2 section
    } else {
        int i = (blk - 256) * 256 + threadIdx.x;   // 0 .. CIN*NHID-1
        int c = i >> 9, n = i & 511;
        g_W1T[(size_t)c * NHID + n] = W1[(size_t)n * CIN + c];
    }
}

// ---------------- in1 = xtr @ W1T + (b1 + br2); 128x128 tile, 8x8/thread ---------
// Round-11 single-buffer form. Grid mapping: bn from blockIdx.x (fast), bm from
// blockIdx.y -> the 4 N-tiles of one M-tile run consecutively and share the A
// tile through L2 (A streams from DRAM once instead of 4x).
__global__ __launch_bounds__(256)
void k_gemm_in1(const float* __restrict__ b1, const float* __restrict__ br2) {
    __shared__ float As[16][132];   // [k][m]
    __shared__ float Bs[16][132];   // [k][n]
    const float* A = g_xtr;
    const float* B = g_W1T;
    int bm = blockIdx.y * 128, bn = blockIdx.x * 128;
    int tid = threadIdx.x;
    int tx = tid & 15, ty = tid >> 4;
    int arow = tid >> 1, acol = (tid & 1) * 8;
    int brow = tid >> 4, bcol = (tid & 15) * 8;

    float acc[8][8];
#pragma unroll
    for (int i = 0; i < 8; i++)
#pragma unroll
        for (int j = 0; j < 8; j++) acc[i][j] = 0.0f;

    for (int k0 = 0; k0 < CIN; k0 += 16) {
        float4 v0 = *(const float4*)(A + (size_t)(bm + arow) * CIN + k0 + acol);
        float4 v1 = *(const float4*)(A + (size_t)(bm + arow) * CIN + k0 + acol + 4);
        As[acol + 0][arow] = v0.x;
        As[acol + 1][arow] = v0.y;
        As[acol + 2][arow] = v0.z;
        As[acol + 3][arow] = v0.w;
        As[acol + 4][arow] = v1.x;
        As[acol + 5][arow] = v1.y;
        As[acol + 6][arow] = v1.z;
        As[acol + 7][arow] = v1.w;
        *(float4*)&Bs[brow][bcol] =
            *(const float4*)(B + (size_t)(k0 + brow) * NHID + bn + bcol);
        *(float4*)&Bs[brow][bcol + 4] =
            *(const float4*)(B + (size_t)(k0 + brow) * NHID + bn + bcol + 4);
        __syncthreads();
#pragma unroll
        for (int k = 0; k < 16; k++) {
            float4 av0 = *(const float4*)&As[k][ty * 8];
            float4 av1 = *(const float4*)&As[k][ty * 8 + 4];
            float4 bv0 = *(const float4*)&Bs[k][tx * 4];
            float4 bv1 = *(const float4*)&Bs[k][64 + tx * 4];
            float a[8] = {av0.x, av0.y, av0.z, av0.w, av1.x, av1.y, av1.z, av1.w};
            float b[8] = {bv0.x, bv0.y, bv0.z, bv0.w, bv1.x, bv1.y, bv1.z, bv1.w};
#pragma unroll
            for (int i = 0; i < 8; i++) {
#pragma unroll
                for (int j = 0; j < 8; j++) acc[i][j] += a[i] * b[j];
            }
        }
        __syncthreads();
    }
    int col0 = bn + tx * 4;
    int col1 = bn + 64 + tx * 4;
    float bb[8];
#pragma unroll
    for (int j = 0; j < 4; j++) {
        bb[j] = b1[col0 + j] + br2[col0 + j];
        bb[4 + j] = b1[col1 + j] + br2[col1 + j];
    }
#pragma unroll
    for (int i = 0; i < 8; i++) {
        size_t row = (size_t)(bm + ty * 8 + i);
        float4 o0, o1;
        o0.x = acc[i][0] + bb[0];
        o0.y = acc[i][1] + bb[1];
        o0.z = acc[i][2] + bb[2];
        o0.w = acc[i][3] + bb[3];
        o1.x = acc[i][4] + bb[4];
        o1.y = acc[i][5] + bb[5];
        o1.z = acc[i][6] + bb[6];
        o1.w = acc[i][7] + bb[7];
        *(float4*)(g_in1 + row * NHID + col0) = o0;
        *(float4*)(g_in1 + row * NHID + col1) = o1;
    }
}

// ---------------- helpers ----------------------------------------------------------
__device__ __forceinline__ void acc_add(float4& a, const float4& v) {
    a.x += v.x; a.y += v.y; a.z += v.z; a.w += v.w;
}

// 8-neuron-wide walk over a padded list (round-11 form: no manual pipelining —
// the 128-reg budget has no headroom; spills cost more than the overlap gains).
// W points at (g_Wab + tableOff + gt*4); lo at +0, hi at +256 floats (coalesced).
// Accumulation: ascending j, per-neuron order identical to a simple loop -> bit-exact.
__device__ __forceinline__ void walk8(const unsigned short* __restrict__ L, int c,
                                      const float* __restrict__ W,
                                      float4& lo, float4& hi) {
    for (int k = 0; k < c; k += 4) {
        ushort4 jj = *(const ushort4*)(L + k);
        const float* p0 = W + ((int)jj.x << 10);
        const float* p1 = W + ((int)jj.y << 10);
        const float* p2 = W + ((int)jj.z << 10);
        const float* p3 = W + ((int)jj.w << 10);
        float4 l0 = __ldg((const float4*)p0), h0 = __ldg((const float4*)(p0 + 256));
        float4 l1 = __ldg((const float4*)p1), h1 = __ldg((const float4*)(p1 + 256));
        float4 l2 = __ldg((const float4*)p2), h2 = __ldg((const float4*)(p2 + 256));
        float4 l3 = __ldg((const float4*)p3), h3 = __ldg((const float4*)(p3 + 256));
        acc_add(lo, l0); acc_add(hi, h0);
        acc_add(lo, l1); acc_add(hi, h1);
        acc_add(lo, l2); acc_add(hi, h2);
        acc_add(lo, l3); acc_add(hi, h3);
    }
}

// ballot-based ordered compaction of an 8-bit spike byte (lane-major, bit-minor
// = ascending j within the warp's 256-neuron segment). Returns padded count.
__device__ __forceinline__ int compact8(unsigned nib, int lane, int n0,
                                        unsigned short* __restrict__ Lw) {
    unsigned lt = (1u << lane) - 1u;
    int base = 0, ctot = 0;
#pragma unroll
    for (int b = 0; b < 8; b++) {
        unsigned B = __ballot_sync(0xffffffffu, (nib >> b) & 1u);
        base += __popc(B & lt);
        ctot += __popc(B);
    }
    unsigned m = nib;
    while (m) {
        int b = __ffs(m) - 1;
        m &= m - 1u;
        Lw[base++] = (unsigned short)(n0 + b);
    }
    int cpad = (ctot + 3) & ~3;
    if (lane < cpad - ctot) Lw[ctot + lane] = (unsigned short)ZROW;
    return cpad;
}

// LIF update for 4 neurons; expressions textually identical to prior rounds.
__device__ __forceinline__ unsigned lif4(float4& mem, float4& sp, float4& cnt,
                                         const float4 tau, const float4 vth,
                                         const float4 inp) {
    mem.x = tau.x * mem.x * (1.f - sp.x) + inp.x;
    mem.y = tau.y * mem.y * (1.f - sp.y) + inp.y;
    mem.z = tau.z * mem.z * (1.f - sp.z) + inp.z;
    mem.w = tau.w * mem.w * (1.f - sp.w) + inp.w;
    float sx = (mem.x > vth.x) ? 1.f : 0.f;
    float sy = (mem.y > vth.y) ? 1.f : 0.f;
    float sz = (mem.z > vth.z) ? 1.f : 0.f;
    float sw = (mem.w > vth.w) ? 1.f : 0.f;
    sp = make_float4(sx, sy, sz, sw);
    cnt.x += sx; cnt.y += sy; cnt.z += sz; cnt.w += sw;
    return (sx > 0.f ? 1u : 0u) | (sy > 0.f ? 2u : 0u) |
           (sz > 0.f ? 4u : 0u) | (sw > 0.f ? 8u : 0u);
}

// ---------------- persistent per-block recurrent kernel (no grid sync) -----------
// Warps 0-1: layer 1.  Warps 2-3: layer 2 + readout.  They run CONCURRENTLY:
// both layers' inputs (s1[p-1], s2[p-2], in1[p]) are available at phase start.
__global__ __launch_bounds__(NT, 4)
void k_rsnn(const float* __restrict__ W4,
            const float* __restrict__ b2, const float* __restrict__ br2,
            const float* __restrict__ b4,
            const float* __restrict__ Vth1, const float* __restrict__ tau1,
            const float* __restrict__ Vth2, const float* __restrict__ tau2,
            const float* __restrict__ tau_out,
            float* __restrict__ out) {
    __shared__ float2 W4sh[NHID];
    __shared__ __align__(16) unsigned short slist1[2][2][256];  // [buf][warpseg]
    __shared__ __align__(16) unsigned short slist2[2][2][256];
    __shared__ int scnt1[2][2];
    __shared__ int scnt2[2][2];
    __shared__ float redx[2][2];
    __shared__ float redy[2][2];

    const int tid = threadIdx.x;
    const int grp = tid >> 6;                // 0 = layer1, 1 = layer2
    const int gt = tid & 63;                 // thread in group
    const int n0 = gt * 8;                   // neurons n0..n0+7 (of its layer)
    const int lane = tid & 31;
    const int gw = (tid >> 5) & 1;           // warp within group (segment id)
    const int rowg = blockIdx.x;             // global batch row

    for (int i = tid; i < NHID; i += NT)
        W4sh[i] = make_float2(W4[i], W4[NHID + i]);
    if (tid < 4) {
        ((int*)scnt1)[tid] = 0;
        ((int*)scnt2)[tid] = 0;
    }
    __syncthreads();

    const float4 z4 = make_float4(0.f, 0.f, 0.f, 0.f);
    // per-group parameters for this thread's 8 neurons
    float4 tau_lo, tau_hi, vth_lo, vth_hi, bias_lo = z4, bias_hi = z4;
    if (grp == 0) {
        tau_lo = *(const float4*)(tau1 + n0);
        tau_hi = *(const float4*)(tau1 + n0 + 4);
        vth_lo = *(const float4*)(Vth1 + n0);
        vth_hi = *(const float4*)(Vth1 + n0 + 4);
    } else {
        tau_lo = *(const float4*)(tau2 + n0);
        tau_hi = *(const float4*)(tau2 + n0 + 4);
        vth_lo = *(const float4*)(Vth2 + n0);
        vth_hi = *(const float4*)(Vth2 + n0 + 4);
        bias_lo.x = b2[n0 + 0] + br2[n0 + 0];
        bias_lo.y = b2[n0 + 1] + br2[n0 + 1];
        bias_lo.z = b2[n0 + 2] + br2[n0 + 2];
        bias_lo.w = b2[n0 + 3] + br2[n0 + 3];
        bias_hi.x = b2[n0 + 4] + br2[n0 + 4];
        bias_hi.y = b2[n0 + 5] + br2[n0 + 5];
        bias_hi.z = b2[n0 + 6] + br2[n0 + 6];
        bias_hi.w = b2[n0 + 7] + br2[n0 + 7];
    }

    float4 mem_lo = z4, mem_hi = z4, sp_lo = z4, sp_hi = z4, cnt_lo = z4, cnt_hi = z4;
    unsigned nib2_prev = 0u;                 // layer-2 group: s2[t] byte from prev phase
    float memo_x = 0.f, memo_y = 0.f;        // thread 64 only
    const float to0 = tau_out[0], to1 = tau_out[1];
    const float b40 = b4[0], b41 = b4[1];

    const float* __restrict__ WAB = g_Wab;
    const float* Wrec = WAB + gt * 4;        // Wr2 slice (lo at +0, hi at +256)
    const float* Wff  = WAB + 512 + gt * 4;  // W2 slice

    for (int p = 0; p <= T_STEPS + 1; p++) {
        const int rb1 = (p + 1) & 1;          // buf holding s1[p-1]
        const int rb2 = p & 1;                // buf holding s2[p-2]

        if (grp == 0) {
            // ================= LAYER 1, t = p =================
            if (p < T_STEPS) {
                float4 i1_lo = __ldcg((const float4*)(g_in1 + ((size_t)p * BATCH + rowg) * NHID + n0));
                float4 i1_hi = __ldcg((const float4*)(g_in1 + ((size_t)p * BATCH + rowg) * NHID + n0 + 4));
                float4 a_lo = z4, a_hi = z4;
#pragma unroll
                for (int w = 0; w < 2; w++)
                    walk8(slist1[rb1][w], scnt1[rb1][w], Wrec, a_lo, a_hi);
                i1_lo.x += a_lo.x; i1_lo.y += a_lo.y; i1_lo.z += a_lo.z; i1_lo.w += a_lo.w;
                i1_hi.x += a_hi.x; i1_hi.y += a_hi.y; i1_hi.z += a_hi.z; i1_hi.w += a_hi.w;
                unsigned nib = lif4(mem_lo, sp_lo, cnt_lo, tau_lo, vth_lo, i1_lo);
                nib |= lif4(mem_hi, sp_hi, cnt_hi, tau_hi, vth_hi, i1_hi) << 4;
                int cpad = compact8(nib, lane, n0, slist1[p & 1][gw]);
                if (lane == 0) scnt1[p & 1][gw] = cpad;
            }
        } else {
            // ================= LAYER 2, t = p-1, + readout t = p-2 =================
            unsigned nib2_new = 0u;
            if (p >= 1 && p <= T_STEPS) {
                float4 r_lo = z4, r_hi = z4;     // Wr2 @ s2[p-2]
                float4 f_lo = z4, f_hi = z4;     // W2  @ s1[p-1]
#pragma unroll
                for (int w = 0; w < 2; w++)
                    walk8(slist2[rb2][w], scnt2[rb2][w], Wrec, r_lo, r_hi);
#pragma unroll
                for (int w = 0; w < 2; w++)
                    walk8(slist1[rb1][w], scnt1[rb1][w], Wff, f_lo, f_hi);
                float4 i2_lo, i2_hi;
                i2_lo.x = f_lo.x + r_lo.x + bias_lo.x;
                i2_lo.y = f_lo.y + r_lo.y + bias_lo.y;
                i2_lo.z = f_lo.z + r_lo.z + bias_lo.z;
                i2_lo.w = f_lo.w + r_lo.w + bias_lo.w;
                i2_hi.x = f_hi.x + r_hi.x + bias_hi.x;
                i2_hi.y = f_hi.y + r_hi.y + bias_hi.y;
                i2_hi.z = f_hi.z + r_hi.z + bias_hi.z;
                i2_hi.w = f_hi.w + r_hi.w + bias_hi.w;
                nib2_new = lif4(mem_lo, sp_lo, cnt_lo, tau_lo, vth_lo, i2_lo);
                nib2_new |= lif4(mem_hi, sp_hi, cnt_hi, tau_hi, vth_hi, i2_hi) << 4;
                int cpad = compact8(nib2_new, lane, n0, slist2[(p + 1) & 1][gw]);
                if (lane == 0) scnt2[(p + 1) & 1][gw] = cpad;
            }

            // readout partials for t = p-2 (uses nib2_prev = s2[p-2])
            {
                float ax = 0.f, ay = 0.f;
                unsigned nb = nib2_prev;
#pragma unroll
                for (int b = 0; b < 8; b++) {
                    if (nb & (1u << b)) {
                        float2 t = W4sh[n0 + b];
                        ax += t.x;
                        ay += t.y;
                    }
                }
#pragma unroll
                for (int off = 16; off > 0; off >>= 1) {
                    ax += __shfl_down_sync(0xffffffffu, ax, off);
                    ay += __shfl_down_sync(0xffffffffu, ay, off);
                }
                if (lane == 0) {
                    redx[p & 1][gw] = ax;
                    redy[p & 1][gw] = ay;
                }
            }
            nib2_prev = nib2_new;
        }

        __syncthreads();   // the ONLY sync per phase (4 warps)

        // ---- finalize readout t = p-2 (one thread of layer-2 group) ----
        if (p >= 2 && tid == 64) {
            int par = p & 1;
            float ax = redx[par][0] + redx[par][1];
            float ay = redy[par][0] + redy[par][1];
            memo_x = to0 * memo_x + ax + b40;
            memo_y = to1 * memo_y + ay + b41;
            int t = p - 2;
            out[(size_t)rowg * (2 * T_STEPS) + t] = memo_x;
            out[(size_t)rowg * (2 * T_STEPS) + T_STEPS + t] = memo_y;
        }
    }

    // ---- spike-count outputs ----
    const float inv = 1.f / (float)T_STEPS;
    float* sc1 = out + (size_t)BATCH * 2 * T_STEPS;
    float* sc2 = sc1 + (size_t)BATCH * NHID;
    float* dst = (grp == 0) ? sc1 : sc2;
    *(float4*)(dst + (size_t)rowg * NHID + n0) =
        make_float4(cnt_lo.x * inv, cnt_lo.y * inv, cnt_lo.z * inv, cnt_lo.w * inv);
    *(float4*)(dst + (size_t)rowg * NHID + n0 + 4) =
        make_float4(cnt_hi.x * inv, cnt_hi.y * inv, cnt_hi.z * inv, cnt_hi.w * inv);
}

// ---------------- launch ----------------------------------------------------------
extern "C" void kernel_launch(void* const* d_in, const int* in_sizes, int n_in,
                              void* d_out, int out_size) {
    (void)in_sizes; (void)n_in; (void)out_size;
    const float* x    = (const float*)d_in[0];
    const float* W1   = (const float*)d_in[1];
    const float* b1   = (const float*)d_in[2];
    const float* W2   = (const float*)d_in[3];
    const float* b2   = (const float*)d_in[4];
    const float* Wr2  = (const float*)d_in[5];
    const float* br2  = (const float*)d_in[6];
    // d_in[7..10]: W3, b3, Wr3, br3 — dead (layer 3 never reaches outputs)
    const float* W4   = (const float*)d_in[11];
    const float* b4   = (const float*)d_in[12];
    const float* Vth1 = (const float*)d_in[13];
    const float* tau1 = (const float*)d_in[14];
    const float* Vth2 = (const float*)d_in[15];
    const float* tau2 = (const float*)d_in[16];
    // d_in[17..18]: Vth3, tau3 — dead
    const float* tau_out = (const float*)d_in[19];
    float* out = (float*)d_out;

    k_transpose_x<<<dim3((T_STEPS + 31) / 32, CIN / 32, BATCH), dim3(32, 8)>>>(x);
    k_prep<<<512, 256>>>(W1, Wr2, W2);
    // N-tiles fastest -> consecutive blocks reuse the same A tile via L2
    k_gemm_in1<<<dim3(NHID / 128, (T_STEPS * BATCH) / 128), 256>>>(b1, br2);
    k_rsnn<<<NBLK, NT>>>(W4, b2, br2, b4, Vth1, tau1, Vth2, tau2, tau_out, out);
}